// round 11
// baseline (speedup 1.0000x reference)
#include <cuda_runtime.h>

#define N_NODES 100000
#define N_EDGES 3200000
#define N_FEAT  512
#define N_HID   16
#define N_CLS   7

#define SCAN_BLK   1024
#define SCAN_GRID  98            // 98*1024 = 100352 >= N_NODES
#define SCAN_TOT   (SCAN_GRID * SCAN_BLK)
#define EDGEB      3125          // 3125 * 256 threads * 4 edges = 3.2M
#define GROWS      8             // rows per gemm tile

// Scratch (device globals; no allocation allowed).
// Zero-recycling invariants (device globals zero-initialized at load):
//  - g_deg zeroed by scan_kernel after consumption -> next call's hist starts at 0.
//  - g_scan_pkt zeroed by hist_kernel block 0 (serialized before scan).
__device__ __align__(128) float g_h   [N_NODES * N_HID];  // x @ W1
__device__ __align__(128) float g_h2  [N_NODES * 8];      // relu(agg1+b1) @ W2, padded
__device__ __align__(128) int   g_deg [SCAN_TOT];         // per-dst degree
__device__ __align__(128) int   g_off [SCAN_TOT];         // CSR offsets (exclusive scan)
__device__ __align__(128) int   g_pos [N_EDGES];          // within-segment position
__device__ __align__(128) int   g_srcs[N_EDGES];          // CSR: src ids grouped by dst
__device__ __align__(128) volatile unsigned long long g_scan_pkt[SCAN_GRID]; // (flag<<32)|sum

typedef unsigned long long u64;

__device__ __forceinline__ u64 pack2(float a, float b) {
    u64 r; asm("mov.b64 %0, {%1,%2};" : "=l"(r) : "f"(a), "f"(b)); return r;
}
__device__ __forceinline__ void unpack2(u64 v, float& a, float& b) {
    asm("mov.b64 {%0,%1}, %2;" : "=f"(a), "=f"(b) : "l"(v));
}
__device__ __forceinline__ void ffma2(u64& d, u64 a, u64 b) {
    asm("fma.rn.f32x2 %0, %1, %2, %0;" : "+l"(d) : "l"(a), "l"(b));
}
__device__ __forceinline__ void fadd2(u64& d, u64 a) {
    asm("add.rn.f32x2 %0, %0, %1;" : "+l"(d) : "l"(a));
}

// ---------------------------------------------------------------- degree histogram (+position)
__global__ void __launch_bounds__(256, 8)
hist_kernel(const int* __restrict__ ei) {
    if (blockIdx.x == 0 && threadIdx.x < SCAN_GRID)
        g_scan_pkt[threadIdx.x] = 0ull;          // reset lookback state for this call
    int e0 = (blockIdx.x * 256 + threadIdx.x) * 4;
    if (e0 >= N_EDGES) return;
    int4 d4 = *reinterpret_cast<const int4*>(ei + N_EDGES + e0);
    int4 p4;
    p4.x = atomicAdd(&g_deg[d4.x], 1);
    p4.y = atomicAdd(&g_deg[d4.y], 1);
    p4.z = atomicAdd(&g_deg[d4.z], 1);
    p4.w = atomicAdd(&g_deg[d4.w], 1);
    *reinterpret_cast<int4*>(g_pos + e0) = p4;
}

// ---------------------------------------------------------------- single-pass scan (decoupled lookback)
// 98 blocks, all resident in wave 1 -> lookback cannot deadlock.
// Also re-zeroes g_deg for the next call.
__global__ void __launch_bounds__(SCAN_BLK, 1)
scan_kernel() {
    __shared__ int sd[SCAN_BLK];
    __shared__ int sh_prefix;
    const int t = threadIdx.x, b = blockIdx.x;
    const int g = b * SCAN_BLK + t;
    const int val = g_deg[g];
    g_deg[g] = 0;                                // recycle for next call
    sd[t] = val;
    __syncthreads();
    for (int d = 1; d < SCAN_BLK; d <<= 1) {
        int tmp = (t >= d) ? sd[t - d] : 0;
        __syncthreads();
        if (t >= d) sd[t] += tmp;
        __syncthreads();
    }
    const int incl  = sd[t];
    const int total = sd[SCAN_BLK - 1];

    if (t == 0) {
        if (b == 0) { sh_prefix = 0; g_scan_pkt[0] = (2ull << 32) | (unsigned)total; }
        else        { g_scan_pkt[b] = (1ull << 32) | (unsigned)total; }
    }
    __syncthreads();

    if (b > 0 && t < 32) {     // warp 0 lookback, 32-wide windows
        const int lane = t;
        int running = 0;
        int p = b - 1;
        for (;;) {
            int idx = p - lane;
            u64 pkt = 0ull;
            if (idx >= 0) {
                do { pkt = g_scan_pkt[idx]; } while ((unsigned)(pkt >> 32) == 0u);
            }
            unsigned flag = (unsigned)(pkt >> 32);
            unsigned mi = __ballot_sync(0xffffffffu, (idx >= 0) && (flag == 2u));
            int l2 = mi ? (__ffs(mi) - 1) : 32;
            int contrib = ((idx >= 0) && (lane <= l2)) ? (int)(unsigned)pkt : 0;
#pragma unroll
            for (int d = 16; d; d >>= 1) contrib += __shfl_xor_sync(0xffffffffu, contrib, d);
            running += contrib;
            if (mi) break;
            p -= 32;
        }
        if (lane == 0) {
            sh_prefix = running;
            g_scan_pkt[b] = (2ull << 32) | (unsigned)(running + total);
        }
    }
    __syncthreads();
    g_off[g] = sh_prefix + incl - val;
}

// ---------------------------------------------------------------- CSR fill (atomic-free)
__global__ void __launch_bounds__(256, 8)
fill_kernel(const int* __restrict__ ei) {
    int e0 = (blockIdx.x * 256 + threadIdx.x) * 4;
    if (e0 >= N_EDGES) return;
    int4 s4 = *reinterpret_cast<const int4*>(ei + e0);
    int4 d4 = *reinterpret_cast<const int4*>(ei + N_EDGES + e0);
    int4 p4 = *reinterpret_cast<const int4*>(g_pos + e0);
    g_srcs[g_off[d4.x] + p4.x] = s4.x;
    g_srcs[g_off[d4.y] + p4.y] = s4.y;
    g_srcs[g_off[d4.z] + p4.z] = s4.z;
    g_srcs[g_off[d4.w] + p4.w] = s4.w;
}

// ---------------------------------------------------------------- GEMM1: h = x @ W1
// 8-row tiles in smem. Warp w: row-group s = w>>2 (4 rows), col-quad q = w&3
// (4 cols) -> each warp reads only its 4 rows: LDS amplification 4.
// Lane l owns k [16l,16l+16) with W in 32 packed-f32x2 regs. Software
// pipeline: next tile's LDGs issued before current tile's FMA phase.
__global__ void __launch_bounds__(256, 2)
gemm1_kernel(const float* __restrict__ x, const float* __restrict__ W1) {
    __shared__ float4 xs[GROWS * 128];   // 16KB, XOR-swizzled granules
    const int tid = threadIdx.x;
    const int w = tid >> 5, l = tid & 31;
    const int q = w & 3, s = w >> 2;

    u64 wr0[16], wr1[16];
#pragma unroll
    for (int j = 0; j < 16; j++) {
        float4 wv = *reinterpret_cast<const float4*>(W1 + (l * 16 + j) * 16 + q * 4);
        wr0[j] = pack2(wv.x, wv.y);
        wr1[j] = pack2(wv.z, wv.w);
    }

    const float4* x4 = reinterpret_cast<const float4*>(x);
    const int ntiles = N_NODES / GROWS;   // 12500

    int tile = blockIdx.x;
    float4 v0, v1, v2, v3;
    if (tile < ntiles) {
        size_t base = (size_t)tile * (GROWS * 128);
        v0 = x4[base + tid];
        v1 = x4[base + 256 + tid];
        v2 = x4[base + 512 + tid];
        v3 = x4[base + 768 + tid];
    }

    while (tile < ntiles) {
        __syncthreads();      // prior tile's readers done
        {
            int i0 = tid;       xs[i0 ^ ((i0 >> 3) & 7)] = v0;
            int i1 = tid + 256; xs[i1 ^ ((i1 >> 3) & 7)] = v1;
            int i2 = tid + 512; xs[i2 ^ ((i2 >> 3) & 7)] = v2;
            int i3 = tid + 768; xs[i3 ^ ((i3 >> 3) & 7)] = v3;
        }
        __syncthreads();

        const int next = tile + gridDim.x;
        if (next < ntiles) {  // prefetch next tile during compute
            size_t base = (size_t)next * (GROWS * 128);
            v0 = x4[base + tid];
            v1 = x4[base + 256 + tid];
            v2 = x4[base + 512 + tid];
            v3 = x4[base + 768 + tid];
        }

        u64 a0[4], a1[4];
#pragma unroll
        for (int r = 0; r < 4; r++) { a0[r] = 0ull; a1[r] = 0ull; }
#pragma unroll
        for (int r = 0; r < 4; r++) {
            const int row = s * 4 + r;
#pragma unroll
            for (int j4 = 0; j4 < 4; j4++) {
                int g = row * 128 + l * 4 + j4;
                float4 xv = xs[g ^ ((g >> 3) & 7)];
                u64 xx;
                xx = pack2(xv.x, xv.x); ffma2(a0[r], xx, wr0[j4*4+0]); ffma2(a1[r], xx, wr1[j4*4+0]);
                xx = pack2(xv.y, xv.y); ffma2(a0[r], xx, wr0[j4*4+1]); ffma2(a1[r], xx, wr1[j4*4+1]);
                xx = pack2(xv.z, xv.z); ffma2(a0[r], xx, wr0[j4*4+2]); ffma2(a1[r], xx, wr1[j4*4+2]);
                xx = pack2(xv.w, xv.w); ffma2(a0[r], xx, wr0[j4*4+3]); ffma2(a1[r], xx, wr1[j4*4+3]);
            }
        }
        // 8 independent butterfly reductions (pipelined)
#pragma unroll
        for (int r = 0; r < 4; r++) {
#pragma unroll
            for (int d = 16; d; d >>= 1) {
                u64 t0 = __shfl_xor_sync(0xffffffffu, a0[r], d);
                u64 t1 = __shfl_xor_sync(0xffffffffu, a1[r], d);
                fadd2(a0[r], t0); fadd2(a1[r], t1);
            }
        }
        if (l == 0) {
#pragma unroll
            for (int r = 0; r < 4; r++) {
                float c0, c1, c2, c3;
                unpack2(a0[r], c0, c1);
                unpack2(a1[r], c2, c3);
                *reinterpret_cast<float4*>(g_h + (tile * GROWS + s * 4 + r) * 16 + q * 4)
                    = make_float4(c0, c1, c2, c3);
            }
        }
        tile = next;
    }
}

// ---------------------------------------------------------------- gather1 + fused relu/W2
// Warp per node. Lane = slot*16 + f: feature in lane (coalesced row reads), 2 edge slots.
__global__ void __launch_bounds__(256, 8)
gather1_kernel(const float* __restrict__ W2, const float* __restrict__ b1) {
    const int lane = threadIdx.x & 31;
    const int wid  = threadIdx.x >> 5;
    const int f    = lane & 15;
    const int slot = lane >> 4;
    const int warp_global = blockIdx.x * 8 + wid;
    const int n_warps = gridDim.x * 8;

    float w2r[7];
#pragma unroll
    for (int cc = 0; cc < 7; cc++) w2r[cc] = __ldg(W2 + f * 7 + cc);
    const float b1f = __ldg(b1 + f);

    for (int n = warp_global; n < N_NODES; n += n_warps) {
        const int start = g_off[n];
        const int end   = g_off[n + 1];

        float a0 = 0.f, a1 = 0.f, a2 = 0.f, a3 = 0.f;
        int i = start + slot;
        for (; i + 6 < end; i += 8) {
            int s0 = g_srcs[i];
            int s1 = g_srcs[i + 2];
            int s2 = g_srcs[i + 4];
            int s3 = g_srcs[i + 6];
            a0 += g_h[s0 * 16 + f];
            a1 += g_h[s1 * 16 + f];
            a2 += g_h[s2 * 16 + f];
            a3 += g_h[s3 * 16 + f];
        }
        for (; i < end; i += 2) a0 += g_h[g_srcs[i] * 16 + f];
        float acc = (a0 + a1) + (a2 + a3);
        acc += __shfl_xor_sync(0xffffffffu, acc, 16);

        float r = fmaxf(acc + b1f, 0.f);
        float po[7];
#pragma unroll
        for (int cc = 0; cc < 7; cc++) po[cc] = r * w2r[cc];
#pragma unroll
        for (int d = 8; d; d >>= 1) {
#pragma unroll
            for (int cc = 0; cc < 7; cc++)
                po[cc] += __shfl_xor_sync(0xffffffffu, po[cc], d);
        }
        if (lane == 0) {
            float4* op = reinterpret_cast<float4*>(g_h2) + n * 2;
            op[0] = make_float4(po[0], po[1], po[2], po[3]);
            op[1] = make_float4(po[4], po[5], po[6], 0.f);
        }
    }
}

// ---------------------------------------------------------------- gather2 + fused log_softmax
__global__ void __launch_bounds__(256, 8)
gather2_kernel(const float* __restrict__ b2, float* __restrict__ out) {
    const int lane = threadIdx.x & 31;
    const int wid  = threadIdx.x >> 5;
    const int f    = lane & 7;
    const int slot = lane >> 3;        // 0..3
    const int warp_global = blockIdx.x * 8 + wid;
    const int n_warps = gridDim.x * 8;

    const float b2f = (f < 7) ? __ldg(b2 + f) : 0.f;

    for (int n = warp_global; n < N_NODES; n += n_warps) {
        const int start = g_off[n];
        const int end   = g_off[n + 1];

        float a0 = 0.f, a1 = 0.f, a2 = 0.f, a3 = 0.f;
        int i = start + slot;
        for (; i + 12 < end; i += 16) {
            int s0 = g_srcs[i];
            int s1 = g_srcs[i + 4];
            int s2 = g_srcs[i + 8];
            int s3 = g_srcs[i + 12];
            a0 += g_h2[s0 * 8 + f];
            a1 += g_h2[s1 * 8 + f];
            a2 += g_h2[s2 * 8 + f];
            a3 += g_h2[s3 * 8 + f];
        }
        for (; i < end; i += 4) a0 += g_h2[g_srcs[i] * 8 + f];
        float acc = (a0 + a1) + (a2 + a3);
        acc += __shfl_xor_sync(0xffffffffu, acc, 16);
        acc += __shfl_xor_sync(0xffffffffu, acc, 8);

        float v = acc + b2f;
        float m = (f < 7) ? v : -3.0e38f;
#pragma unroll
        for (int d = 4; d; d >>= 1) m = fmaxf(m, __shfl_xor_sync(0xffffffffu, m, d));
        float ex = (f < 7) ? expf(v - m) : 0.f;
        float ssum = ex;
#pragma unroll
        for (int d = 4; d; d >>= 1) ssum += __shfl_xor_sync(0xffffffffu, ssum, d);
        float lse = m + logf(ssum);
        if (slot == 0 && f < 7) out[(size_t)n * 7 + f] = v - lse;
    }
}

// ----------------------------------------------------------------
// Inputs identified by element count (pairwise distinct):
//   x: 51,200,000  edge_index: 6,400,000  W1: 8,192  W2: 112  b1: 16  b2: 7
//
// Fork-join overlap: gemm1 (independent of the CSR build) runs on a side
// non-blocking stream, joined before gather1. Streams/events are created once
// at first call (the uncaptured correctness run); every call performs the
// identical launch sequence -> deterministic, graph-capturable fork-join.
extern "C" void kernel_launch(void* const* d_in, const int* in_sizes, int n_in,
                              void* d_out, int out_size) {
    const float* x  = nullptr;
    const int*   ei = nullptr;
    const float* W1 = nullptr;
    const float* b1 = nullptr;
    const float* W2 = nullptr;
    const float* b2 = nullptr;

    for (int i = 0; i < n_in; i++) {
        switch (in_sizes[i]) {
            case N_NODES * N_FEAT: x  = (const float*)d_in[i]; break;
            case 2 * N_EDGES:      ei = (const int*)d_in[i];   break;
            case N_FEAT * N_HID:   W1 = (const float*)d_in[i]; break;
            case N_HID:            b1 = (const float*)d_in[i]; break;
            case N_HID * N_CLS:    W2 = (const float*)d_in[i]; break;
            case N_CLS:            b2 = (const float*)d_in[i]; break;
            default: break;
        }
    }
    float* out = (float*)d_out;

    static cudaStream_t s2 = []() {
        cudaStream_t s; cudaStreamCreateWithFlags(&s, cudaStreamNonBlocking); return s;
    }();
    static cudaEvent_t evFork = []() {
        cudaEvent_t e; cudaEventCreateWithFlags(&e, cudaEventDisableTiming); return e;
    }();
    static cudaEvent_t evJoin = []() {
        cudaEvent_t e; cudaEventCreateWithFlags(&e, cudaEventDisableTiming); return e;
    }();

    // fork: gemm1 on s2, CSR build on the main (legacy) stream
    cudaEventRecord(evFork, 0);
    cudaStreamWaitEvent(s2, evFork, 0);
    gemm1_kernel<<<296, 256, 0, s2>>>(x, W1);
    cudaEventRecord(evJoin, s2);

    hist_kernel<<<EDGEB, 256>>>(ei);
    scan_kernel<<<SCAN_GRID, SCAN_BLK>>>();
    fill_kernel<<<EDGEB, 256>>>(ei);

    // join: gathers need both g_srcs/g_off (main) and g_h (s2)
    cudaStreamWaitEvent(0, evJoin, 0);
    gather1_kernel<<<1184, 256>>>(W2, b1);
    gather2_kernel<<<1184, 256>>>(b2, out);
}

// round 12
// speedup vs baseline: 1.0937x; 1.0937x over previous
#include <cuda_runtime.h>

#define N_NODES 100000
#define N_EDGES 3200000
#define N_FEAT  512
#define N_HID   16
#define N_CLS   7

#define SCAN_BLK   1024
#define SCAN_GRID  98            // 98*1024 = 100352 >= N_NODES
#define SCAN_TOT   (SCAN_GRID * SCAN_BLK)
#define EDGEB      3125          // 3125 * 256 threads * 4 edges = 3.2M
#define GROWS      8             // rows per gemm tile

// Scratch (device globals; no allocation allowed).
// Zero-recycling invariants (device globals zero-initialized at load):
//  - g_deg zeroed by scan_kernel after consumption -> next call's hist starts at 0.
//  - g_scan_pkt zeroed by hist_kernel block 0 (serialized before scan).
__device__ __align__(128) float g_h   [N_NODES * N_HID];  // x @ W1
__device__ __align__(128) float g_h2  [N_NODES * 8];      // relu(agg1+b1) @ W2, padded
__device__ __align__(128) int   g_deg [SCAN_TOT];         // per-dst degree
__device__ __align__(128) int   g_off [SCAN_TOT];         // CSR offsets (exclusive scan)
__device__ __align__(128) int   g_pos [N_EDGES];          // within-segment position
__device__ __align__(128) int   g_srcs[N_EDGES];          // CSR: src ids grouped by dst
__device__ __align__(128) volatile unsigned long long g_scan_pkt[SCAN_GRID]; // (flag<<32)|sum

typedef unsigned long long u64;

__device__ __forceinline__ u64 pack2(float a, float b) {
    u64 r; asm("mov.b64 %0, {%1,%2};" : "=l"(r) : "f"(a), "f"(b)); return r;
}
__device__ __forceinline__ void unpack2(u64 v, float& a, float& b) {
    asm("mov.b64 {%0,%1}, %2;" : "=f"(a), "=f"(b) : "l"(v));
}
__device__ __forceinline__ void ffma2(u64& d, u64 a, u64 b) {
    asm("fma.rn.f32x2 %0, %1, %2, %0;" : "+l"(d) : "l"(a), "l"(b));
}
__device__ __forceinline__ void fadd2(u64& d, u64 a) {
    asm("add.rn.f32x2 %0, %0, %1;" : "+l"(d) : "l"(a));
}

// ---------------------------------------------------------------- degree histogram (+position)
__global__ void __launch_bounds__(256, 8)
hist_kernel(const int* __restrict__ ei) {
    if (blockIdx.x == 0 && threadIdx.x < SCAN_GRID)
        g_scan_pkt[threadIdx.x] = 0ull;          // reset lookback state for this call
    int e0 = (blockIdx.x * 256 + threadIdx.x) * 4;
    if (e0 >= N_EDGES) return;
    int4 d4 = *reinterpret_cast<const int4*>(ei + N_EDGES + e0);
    int4 p4;
    p4.x = atomicAdd(&g_deg[d4.x], 1);
    p4.y = atomicAdd(&g_deg[d4.y], 1);
    p4.z = atomicAdd(&g_deg[d4.z], 1);
    p4.w = atomicAdd(&g_deg[d4.w], 1);
    *reinterpret_cast<int4*>(g_pos + e0) = p4;
}

// ---------------------------------------------------------------- single-pass scan (decoupled lookback)
// 98 blocks, all resident in wave 1 -> lookback cannot deadlock.
// Also re-zeroes g_deg for the next call.
__global__ void __launch_bounds__(SCAN_BLK, 1)
scan_kernel() {
    __shared__ int sd[SCAN_BLK];
    __shared__ int sh_prefix;
    const int t = threadIdx.x, b = blockIdx.x;
    const int g = b * SCAN_BLK + t;
    const int val = g_deg[g];
    g_deg[g] = 0;                                // recycle for next call
    sd[t] = val;
    __syncthreads();
    for (int d = 1; d < SCAN_BLK; d <<= 1) {
        int tmp = (t >= d) ? sd[t - d] : 0;
        __syncthreads();
        if (t >= d) sd[t] += tmp;
        __syncthreads();
    }
    const int incl  = sd[t];
    const int total = sd[SCAN_BLK - 1];

    if (t == 0) {
        if (b == 0) { sh_prefix = 0; g_scan_pkt[0] = (2ull << 32) | (unsigned)total; }
        else        { g_scan_pkt[b] = (1ull << 32) | (unsigned)total; }
    }
    __syncthreads();

    if (b > 0 && t < 32) {     // warp 0 lookback, 32-wide windows
        const int lane = t;
        int running = 0;
        int p = b - 1;
        for (;;) {
            int idx = p - lane;
            u64 pkt = 0ull;
            if (idx >= 0) {
                do { pkt = g_scan_pkt[idx]; } while ((unsigned)(pkt >> 32) == 0u);
            }
            unsigned flag = (unsigned)(pkt >> 32);
            unsigned mi = __ballot_sync(0xffffffffu, (idx >= 0) && (flag == 2u));
            int l2 = mi ? (__ffs(mi) - 1) : 32;
            int contrib = ((idx >= 0) && (lane <= l2)) ? (int)(unsigned)pkt : 0;
#pragma unroll
            for (int d = 16; d; d >>= 1) contrib += __shfl_xor_sync(0xffffffffu, contrib, d);
            running += contrib;
            if (mi) break;
            p -= 32;
        }
        if (lane == 0) {
            sh_prefix = running;
            g_scan_pkt[b] = (2ull << 32) | (unsigned)(running + total);
        }
    }
    __syncthreads();
    g_off[g] = sh_prefix + incl - val;
}

// ---------------------------------------------------------------- CSR fill (atomic-free)
__global__ void __launch_bounds__(256, 8)
fill_kernel(const int* __restrict__ ei) {
    int e0 = (blockIdx.x * 256 + threadIdx.x) * 4;
    if (e0 >= N_EDGES) return;
    int4 s4 = *reinterpret_cast<const int4*>(ei + e0);
    int4 d4 = *reinterpret_cast<const int4*>(ei + N_EDGES + e0);
    int4 p4 = *reinterpret_cast<const int4*>(g_pos + e0);
    g_srcs[g_off[d4.x] + p4.x] = s4.x;
    g_srcs[g_off[d4.y] + p4.y] = s4.y;
    g_srcs[g_off[d4.z] + p4.z] = s4.z;
    g_srcs[g_off[d4.w] + p4.w] = s4.w;
}

// ---------------------------------------------------------------- GEMM1: h = x @ W1
// 8-row tiles in smem, plain row-major float4 (NO swizzle). Warp w: row-group
// s = w>>2 (4 rows), col-quad q = w&3 (4 cols). Lane l owns
// k in { j4*128 + 4l .. +3 : j4=0..3 } so the FMA-phase smem read address is
// row*128 + j4*32 + l -> 32 CONSECUTIVE granules per warp instr: conflict-free
// by construction. W in 32 packed-f32x2 regs. Software-pipelined prefetch.
__global__ void __launch_bounds__(256, 2)
gemm1_kernel(const float* __restrict__ x, const float* __restrict__ W1) {
    __shared__ float4 xs[GROWS * 128];   // 16KB, row-major
    const int tid = threadIdx.x;
    const int w = tid >> 5, l = tid & 31;
    const int q = w & 3, s = w >> 2;

    u64 wr0[16], wr1[16];
#pragma unroll
    for (int j4 = 0; j4 < 4; j4++) {
#pragma unroll
        for (int e = 0; e < 4; e++) {
            int k = j4 * 128 + 4 * l + e;
            float4 wv = *reinterpret_cast<const float4*>(W1 + k * 16 + q * 4);
            wr0[j4 * 4 + e] = pack2(wv.x, wv.y);
            wr1[j4 * 4 + e] = pack2(wv.z, wv.w);
        }
    }

    const float4* x4 = reinterpret_cast<const float4*>(x);
    const int ntiles = N_NODES / GROWS;   // 12500

    int tile = blockIdx.x;
    float4 v0, v1, v2, v3;
    if (tile < ntiles) {
        size_t base = (size_t)tile * (GROWS * 128);
        v0 = x4[base + tid];
        v1 = x4[base + 256 + tid];
        v2 = x4[base + 512 + tid];
        v3 = x4[base + 768 + tid];
    }

    while (tile < ntiles) {
        __syncthreads();      // prior tile's readers done
        xs[tid]       = v0;
        xs[tid + 256] = v1;
        xs[tid + 512] = v2;
        xs[tid + 768] = v3;
        __syncthreads();

        const int next = tile + gridDim.x;
        if (next < ntiles) {  // prefetch next tile during compute
            size_t base = (size_t)next * (GROWS * 128);
            v0 = x4[base + tid];
            v1 = x4[base + 256 + tid];
            v2 = x4[base + 512 + tid];
            v3 = x4[base + 768 + tid];
        }

        u64 a0[4], a1[4];
#pragma unroll
        for (int r = 0; r < 4; r++) { a0[r] = 0ull; a1[r] = 0ull; }
#pragma unroll
        for (int r = 0; r < 4; r++) {
            const int row = s * 4 + r;
#pragma unroll
            for (int j4 = 0; j4 < 4; j4++) {
                float4 xv = xs[row * 128 + j4 * 32 + l];   // consecutive granules
                u64 xx;
                xx = pack2(xv.x, xv.x); ffma2(a0[r], xx, wr0[j4*4+0]); ffma2(a1[r], xx, wr1[j4*4+0]);
                xx = pack2(xv.y, xv.y); ffma2(a0[r], xx, wr0[j4*4+1]); ffma2(a1[r], xx, wr1[j4*4+1]);
                xx = pack2(xv.z, xv.z); ffma2(a0[r], xx, wr0[j4*4+2]); ffma2(a1[r], xx, wr1[j4*4+2]);
                xx = pack2(xv.w, xv.w); ffma2(a0[r], xx, wr0[j4*4+3]); ffma2(a1[r], xx, wr1[j4*4+3]);
            }
        }
        // 8 independent butterfly reductions (pipelined)
#pragma unroll
        for (int r = 0; r < 4; r++) {
#pragma unroll
            for (int d = 16; d; d >>= 1) {
                u64 t0 = __shfl_xor_sync(0xffffffffu, a0[r], d);
                u64 t1 = __shfl_xor_sync(0xffffffffu, a1[r], d);
                fadd2(a0[r], t0); fadd2(a1[r], t1);
            }
        }
        if (l == 0) {
#pragma unroll
            for (int r = 0; r < 4; r++) {
                float c0, c1, c2, c3;
                unpack2(a0[r], c0, c1);
                unpack2(a1[r], c2, c3);
                *reinterpret_cast<float4*>(g_h + (tile * GROWS + s * 4 + r) * 16 + q * 4)
                    = make_float4(c0, c1, c2, c3);
            }
        }
        tile = next;
    }
}

// ---------------------------------------------------------------- gather1 + fused relu/W2
// Warp per node. Lane = slot*16 + f: feature in lane (coalesced row reads), 2 edge slots.
__global__ void __launch_bounds__(256, 8)
gather1_kernel(const float* __restrict__ W2, const float* __restrict__ b1) {
    const int lane = threadIdx.x & 31;
    const int wid  = threadIdx.x >> 5;
    const int f    = lane & 15;
    const int slot = lane >> 4;
    const int warp_global = blockIdx.x * 8 + wid;
    const int n_warps = gridDim.x * 8;

    float w2r[7];
#pragma unroll
    for (int cc = 0; cc < 7; cc++) w2r[cc] = __ldg(W2 + f * 7 + cc);
    const float b1f = __ldg(b1 + f);

    for (int n = warp_global; n < N_NODES; n += n_warps) {
        const int start = g_off[n];
        const int end   = g_off[n + 1];

        float a0 = 0.f, a1 = 0.f, a2 = 0.f, a3 = 0.f;
        int i = start + slot;
        for (; i + 6 < end; i += 8) {
            int s0 = g_srcs[i];
            int s1 = g_srcs[i + 2];
            int s2 = g_srcs[i + 4];
            int s3 = g_srcs[i + 6];
            a0 += g_h[s0 * 16 + f];
            a1 += g_h[s1 * 16 + f];
            a2 += g_h[s2 * 16 + f];
            a3 += g_h[s3 * 16 + f];
        }
        for (; i < end; i += 2) a0 += g_h[g_srcs[i] * 16 + f];
        float acc = (a0 + a1) + (a2 + a3);
        acc += __shfl_xor_sync(0xffffffffu, acc, 16);

        float r = fmaxf(acc + b1f, 0.f);
        float po[7];
#pragma unroll
        for (int cc = 0; cc < 7; cc++) po[cc] = r * w2r[cc];
#pragma unroll
        for (int d = 8; d; d >>= 1) {
#pragma unroll
            for (int cc = 0; cc < 7; cc++)
                po[cc] += __shfl_xor_sync(0xffffffffu, po[cc], d);
        }
        if (lane == 0) {
            float4* op = reinterpret_cast<float4*>(g_h2) + n * 2;
            op[0] = make_float4(po[0], po[1], po[2], po[3]);
            op[1] = make_float4(po[4], po[5], po[6], 0.f);
        }
    }
}

// ---------------------------------------------------------------- gather2 + fused log_softmax
__global__ void __launch_bounds__(256, 8)
gather2_kernel(const float* __restrict__ b2, float* __restrict__ out) {
    const int lane = threadIdx.x & 31;
    const int wid  = threadIdx.x >> 5;
    const int f    = lane & 7;
    const int slot = lane >> 3;        // 0..3
    const int warp_global = blockIdx.x * 8 + wid;
    const int n_warps = gridDim.x * 8;

    const float b2f = (f < 7) ? __ldg(b2 + f) : 0.f;

    for (int n = warp_global; n < N_NODES; n += n_warps) {
        const int start = g_off[n];
        const int end   = g_off[n + 1];

        float a0 = 0.f, a1 = 0.f, a2 = 0.f, a3 = 0.f;
        int i = start + slot;
        for (; i + 12 < end; i += 16) {
            int s0 = g_srcs[i];
            int s1 = g_srcs[i + 4];
            int s2 = g_srcs[i + 8];
            int s3 = g_srcs[i + 12];
            a0 += g_h2[s0 * 8 + f];
            a1 += g_h2[s1 * 8 + f];
            a2 += g_h2[s2 * 8 + f];
            a3 += g_h2[s3 * 8 + f];
        }
        for (; i < end; i += 4) a0 += g_h2[g_srcs[i] * 8 + f];
        float acc = (a0 + a1) + (a2 + a3);
        acc += __shfl_xor_sync(0xffffffffu, acc, 16);
        acc += __shfl_xor_sync(0xffffffffu, acc, 8);

        float v = acc + b2f;
        float m = (f < 7) ? v : -3.0e38f;
#pragma unroll
        for (int d = 4; d; d >>= 1) m = fmaxf(m, __shfl_xor_sync(0xffffffffu, m, d));
        float ex = (f < 7) ? expf(v - m) : 0.f;
        float ssum = ex;
#pragma unroll
        for (int d = 4; d; d >>= 1) ssum += __shfl_xor_sync(0xffffffffu, ssum, d);
        float lse = m + logf(ssum);
        if (slot == 0 && f < 7) out[(size_t)n * 7 + f] = v - lse;
    }
}

// ----------------------------------------------------------------
// Inputs identified by element count (pairwise distinct):
//   x: 51,200,000  edge_index: 6,400,000  W1: 8,192  W2: 112  b1: 16  b2: 7
extern "C" void kernel_launch(void* const* d_in, const int* in_sizes, int n_in,
                              void* d_out, int out_size) {
    const float* x  = nullptr;
    const int*   ei = nullptr;
    const float* W1 = nullptr;
    const float* b1 = nullptr;
    const float* W2 = nullptr;
    const float* b2 = nullptr;

    for (int i = 0; i < n_in; i++) {
        switch (in_sizes[i]) {
            case N_NODES * N_FEAT: x  = (const float*)d_in[i]; break;
            case 2 * N_EDGES:      ei = (const int*)d_in[i];   break;
            case N_FEAT * N_HID:   W1 = (const float*)d_in[i]; break;
            case N_HID:            b1 = (const float*)d_in[i]; break;
            case N_HID * N_CLS:    W2 = (const float*)d_in[i]; break;
            case N_CLS:            b2 = (const float*)d_in[i]; break;
            default: break;
        }
    }
    float* out = (float*)d_out;

    hist_kernel<<<EDGEB, 256>>>(ei);
    scan_kernel<<<SCAN_GRID, SCAN_BLK>>>();
    fill_kernel<<<EDGEB, 256>>>(ei);
    gemm1_kernel<<<304, 256>>>(x, W1);
    gather1_kernel<<<1184, 256>>>(W2, b1);
    gather2_kernel<<<1184, 256>>>(b2, out);
}

// round 13
// speedup vs baseline: 1.0950x; 1.0012x over previous
#include <cuda_runtime.h>

#define N_NODES 100000
#define N_EDGES 3200000
#define N_FEAT  512
#define N_HID   16
#define N_CLS   7

#define SCAN_BLK   1024
#define SCAN_GRID  98            // 98*1024 = 100352 >= N_NODES
#define SCAN_TOT   (SCAN_GRID * SCAN_BLK)
#define EDGEB      3125          // 3125 * 256 threads * 4 edges = 3.2M
#define GROWS      8             // rows per gemm tile

// Scratch (device globals; no allocation allowed).
// Zero-recycling invariants (device globals zero-initialized at load):
//  - g_deg zeroed by scan_kernel after consumption -> next call's hist starts at 0.
//  - g_scan_pkt zeroed by hist_kernel block 0 (serialized before scan).
__device__ __align__(128) float g_h   [N_NODES * N_HID];  // x @ W1
__device__ __align__(128) float g_h2  [N_NODES * 8];      // relu(agg1+b1) @ W2, padded
__device__ __align__(128) int   g_deg [SCAN_TOT];         // per-dst degree
__device__ __align__(128) int   g_off [SCAN_TOT];         // CSR offsets (exclusive scan)
__device__ __align__(128) int   g_cur [SCAN_TOT];         // absolute fill cursors (copy of off)
__device__ __align__(128) int   g_srcs[N_EDGES];          // CSR: src ids grouped by dst
__device__ __align__(128) volatile unsigned long long g_scan_pkt[SCAN_GRID]; // (flag<<32)|sum

typedef unsigned long long u64;

__device__ __forceinline__ u64 pack2(float a, float b) {
    u64 r; asm("mov.b64 %0, {%1,%2};" : "=l"(r) : "f"(a), "f"(b)); return r;
}
__device__ __forceinline__ void unpack2(u64 v, float& a, float& b) {
    asm("mov.b64 {%0,%1}, %2;" : "=f"(a), "=f"(b) : "l"(v));
}
__device__ __forceinline__ void ffma2(u64& d, u64 a, u64 b) {
    asm("fma.rn.f32x2 %0, %1, %2, %0;" : "+l"(d) : "l"(a), "l"(b));
}
__device__ __forceinline__ void fadd2(u64& d, u64 a) {
    asm("add.rn.f32x2 %0, %0, %1;" : "+l"(d) : "l"(a));
}

// ---------------------------------------------------------------- degree histogram
// Fire-and-forget: atomicAdd return unused -> RED (no return latency).
__global__ void __launch_bounds__(256, 8)
hist_kernel(const int* __restrict__ ei) {
    if (blockIdx.x == 0 && threadIdx.x < SCAN_GRID)
        g_scan_pkt[threadIdx.x] = 0ull;          // reset lookback state for this call
    int e0 = (blockIdx.x * 256 + threadIdx.x) * 4;
    if (e0 >= N_EDGES) return;
    int4 d4 = *reinterpret_cast<const int4*>(ei + N_EDGES + e0);
    atomicAdd(&g_deg[d4.x], 1);
    atomicAdd(&g_deg[d4.y], 1);
    atomicAdd(&g_deg[d4.z], 1);
    atomicAdd(&g_deg[d4.w], 1);
}

// ---------------------------------------------------------------- single-pass scan (decoupled lookback)
// 98 blocks, all resident in wave 1 -> lookback cannot deadlock.
// Re-zeroes g_deg for the next call; writes offsets into BOTH g_off and g_cur.
__global__ void __launch_bounds__(SCAN_BLK, 1)
scan_kernel() {
    __shared__ int sd[SCAN_BLK];
    __shared__ int sh_prefix;
    const int t = threadIdx.x, b = blockIdx.x;
    const int g = b * SCAN_BLK + t;
    const int val = g_deg[g];
    g_deg[g] = 0;                                // recycle for next call
    sd[t] = val;
    __syncthreads();
    for (int d = 1; d < SCAN_BLK; d <<= 1) {
        int tmp = (t >= d) ? sd[t - d] : 0;
        __syncthreads();
        if (t >= d) sd[t] += tmp;
        __syncthreads();
    }
    const int incl  = sd[t];
    const int total = sd[SCAN_BLK - 1];

    if (t == 0) {
        if (b == 0) { sh_prefix = 0; g_scan_pkt[0] = (2ull << 32) | (unsigned)total; }
        else        { g_scan_pkt[b] = (1ull << 32) | (unsigned)total; }
    }
    __syncthreads();

    if (b > 0 && t < 32) {     // warp 0 lookback, 32-wide windows
        const int lane = t;
        int running = 0;
        int p = b - 1;
        for (;;) {
            int idx = p - lane;
            u64 pkt = 0ull;
            if (idx >= 0) {
                do { pkt = g_scan_pkt[idx]; } while ((unsigned)(pkt >> 32) == 0u);
            }
            unsigned flag = (unsigned)(pkt >> 32);
            unsigned mi = __ballot_sync(0xffffffffu, (idx >= 0) && (flag == 2u));
            int l2 = mi ? (__ffs(mi) - 1) : 32;
            int contrib = ((idx >= 0) && (lane <= l2)) ? (int)(unsigned)pkt : 0;
#pragma unroll
            for (int d = 16; d; d >>= 1) contrib += __shfl_xor_sync(0xffffffffu, contrib, d);
            running += contrib;
            if (mi) break;
            p -= 32;
        }
        if (lane == 0) {
            sh_prefix = running;
            g_scan_pkt[b] = (2ull << 32) | (unsigned)(running + total);
        }
    }
    __syncthreads();
    int off = sh_prefix + incl - val;
    g_off[g] = off;
    g_cur[g] = off;
}

// ---------------------------------------------------------------- CSR fill (atomic cursor)
// Cursor starts at the segment offset, so the atomic return IS the absolute slot.
__global__ void __launch_bounds__(256, 8)
fill_kernel(const int* __restrict__ ei) {
    int e0 = (blockIdx.x * 256 + threadIdx.x) * 4;
    if (e0 >= N_EDGES) return;
    int4 s4 = *reinterpret_cast<const int4*>(ei + e0);
    int4 d4 = *reinterpret_cast<const int4*>(ei + N_EDGES + e0);
    int p0 = atomicAdd(&g_cur[d4.x], 1);
    int p1 = atomicAdd(&g_cur[d4.y], 1);
    int p2 = atomicAdd(&g_cur[d4.z], 1);
    int p3 = atomicAdd(&g_cur[d4.w], 1);
    g_srcs[p0] = s4.x;
    g_srcs[p1] = s4.y;
    g_srcs[p2] = s4.z;
    g_srcs[p3] = s4.w;
}

// ---------------------------------------------------------------- GEMM1: h = x @ W1
// 8-row tiles in smem, plain row-major float4 (NO swizzle). Warp w: row-group
// s = w>>2 (4 rows), col-quad q = w&3 (4 cols). Lane l owns
// k in { j4*128 + 4l .. +3 : j4=0..3 } so the FMA-phase smem read address is
// row*128 + j4*32 + l -> conflict-free by construction. W in 32 packed-f32x2
// regs. Software-pipelined prefetch. Reduction: reduce-scatter first step
// (1 SHFL), then 4 butterfly steps on one u64; lanes 0/16 store the pairs.
__global__ void __launch_bounds__(256, 2)
gemm1_kernel(const float* __restrict__ x, const float* __restrict__ W1) {
    __shared__ float4 xs[GROWS * 128];   // 16KB, row-major
    const int tid = threadIdx.x;
    const int w = tid >> 5, l = tid & 31;
    const int q = w & 3, s = w >> 2;
    const bool hi = (l & 16) != 0;

    u64 wr0[16], wr1[16];
#pragma unroll
    for (int j4 = 0; j4 < 4; j4++) {
#pragma unroll
        for (int e = 0; e < 4; e++) {
            int k = j4 * 128 + 4 * l + e;
            float4 wv = *reinterpret_cast<const float4*>(W1 + k * 16 + q * 4);
            wr0[j4 * 4 + e] = pack2(wv.x, wv.y);
            wr1[j4 * 4 + e] = pack2(wv.z, wv.w);
        }
    }

    const float4* x4 = reinterpret_cast<const float4*>(x);
    const int ntiles = N_NODES / GROWS;   // 12500

    int tile = blockIdx.x;
    float4 v0, v1, v2, v3;
    if (tile < ntiles) {
        size_t base = (size_t)tile * (GROWS * 128);
        v0 = x4[base + tid];
        v1 = x4[base + 256 + tid];
        v2 = x4[base + 512 + tid];
        v3 = x4[base + 768 + tid];
    }

    while (tile < ntiles) {
        __syncthreads();      // prior tile's readers done
        xs[tid]       = v0;
        xs[tid + 256] = v1;
        xs[tid + 512] = v2;
        xs[tid + 768] = v3;
        __syncthreads();

        const int next = tile + gridDim.x;
        if (next < ntiles) {  // prefetch next tile during compute
            size_t base = (size_t)next * (GROWS * 128);
            v0 = x4[base + tid];
            v1 = x4[base + 256 + tid];
            v2 = x4[base + 512 + tid];
            v3 = x4[base + 768 + tid];
        }

        u64 a0[4], a1[4];
#pragma unroll
        for (int r = 0; r < 4; r++) { a0[r] = 0ull; a1[r] = 0ull; }
#pragma unroll
        for (int r = 0; r < 4; r++) {
            const int row = s * 4 + r;
#pragma unroll
            for (int j4 = 0; j4 < 4; j4++) {
                float4 xv = xs[row * 128 + j4 * 32 + l];   // consecutive granules
                u64 xx;
                xx = pack2(xv.x, xv.x); ffma2(a0[r], xx, wr0[j4*4+0]); ffma2(a1[r], xx, wr1[j4*4+0]);
                xx = pack2(xv.y, xv.y); ffma2(a0[r], xx, wr0[j4*4+1]); ffma2(a1[r], xx, wr1[j4*4+1]);
                xx = pack2(xv.z, xv.z); ffma2(a0[r], xx, wr0[j4*4+2]); ffma2(a1[r], xx, wr1[j4*4+2]);
                xx = pack2(xv.w, xv.w); ffma2(a0[r], xx, wr0[j4*4+3]); ffma2(a1[r], xx, wr1[j4*4+3]);
            }
        }
        // Reduction per row: reduce-scatter step (d=16) splits pair0/pair1
        // across lane halves, then 4 butterfly steps on a single u64.
#pragma unroll
        for (int r = 0; r < 4; r++) {
            u64 sel  = hi ? a0[r] : a1[r];          // the half we give away
            u64 keep = hi ? a1[r] : a0[r];          // the half we own
            u64 t = __shfl_xor_sync(0xffffffffu, sel, 16);
            fadd2(keep, t);
#pragma unroll
            for (int d = 8; d; d >>= 1) {
                u64 tt = __shfl_xor_sync(0xffffffffu, keep, d);
                fadd2(keep, tt);
            }
            // lane 0 holds cols (4q,4q+1); lane 16 holds cols (4q+2,4q+3)
            if ((l & 15) == 0) {
                float c0, c1; unpack2(keep, c0, c1);
                float2* hp = reinterpret_cast<float2*>(
                    g_h + (tile * GROWS + s * 4 + r) * 16 + q * 4 + (hi ? 2 : 0));
                *hp = make_float2(c0, c1);
            }
        }
        tile = next;
    }
}

// ---------------------------------------------------------------- gather1 + fused relu/W2
// Warp per node. Lane = slot*16 + f: feature in lane (coalesced row reads), 2 edge slots.
__global__ void __launch_bounds__(256, 8)
gather1_kernel(const float* __restrict__ W2, const float* __restrict__ b1) {
    const int lane = threadIdx.x & 31;
    const int wid  = threadIdx.x >> 5;
    const int f    = lane & 15;
    const int slot = lane >> 4;
    const int warp_global = blockIdx.x * 8 + wid;
    const int n_warps = gridDim.x * 8;

    float w2r[7];
#pragma unroll
    for (int cc = 0; cc < 7; cc++) w2r[cc] = __ldg(W2 + f * 7 + cc);
    const float b1f = __ldg(b1 + f);

    for (int n = warp_global; n < N_NODES; n += n_warps) {
        const int start = g_off[n];
        const int end   = g_off[n + 1];

        float a0 = 0.f, a1 = 0.f, a2 = 0.f, a3 = 0.f;
        int i = start + slot;
        for (; i + 6 < end; i += 8) {
            int s0 = g_srcs[i];
            int s1 = g_srcs[i + 2];
            int s2 = g_srcs[i + 4];
            int s3 = g_srcs[i + 6];
            a0 += g_h[s0 * 16 + f];
            a1 += g_h[s1 * 16 + f];
            a2 += g_h[s2 * 16 + f];
            a3 += g_h[s3 * 16 + f];
        }
        for (; i < end; i += 2) a0 += g_h[g_srcs[i] * 16 + f];
        float acc = (a0 + a1) + (a2 + a3);
        acc += __shfl_xor_sync(0xffffffffu, acc, 16);

        float r = fmaxf(acc + b1f, 0.f);
        float po[7];
#pragma unroll
        for (int cc = 0; cc < 7; cc++) po[cc] = r * w2r[cc];
#pragma unroll
        for (int d = 8; d; d >>= 1) {
#pragma unroll
            for (int cc = 0; cc < 7; cc++)
                po[cc] += __shfl_xor_sync(0xffffffffu, po[cc], d);
        }
        if (lane == 0) {
            float4* op = reinterpret_cast<float4*>(g_h2) + n * 2;
            op[0] = make_float4(po[0], po[1], po[2], po[3]);
            op[1] = make_float4(po[4], po[5], po[6], 0.f);
        }
    }
}

// ---------------------------------------------------------------- gather2 + fused log_softmax
__global__ void __launch_bounds__(256, 8)
gather2_kernel(const float* __restrict__ b2, float* __restrict__ out) {
    const int lane = threadIdx.x & 31;
    const int wid  = threadIdx.x >> 5;
    const int f    = lane & 7;
    const int slot = lane >> 3;        // 0..3
    const int warp_global = blockIdx.x * 8 + wid;
    const int n_warps = gridDim.x * 8;

    const float b2f = (f < 7) ? __ldg(b2 + f) : 0.f;

    for (int n = warp_global; n < N_NODES; n += n_warps) {
        const int start = g_off[n];
        const int end   = g_off[n + 1];

        float a0 = 0.f, a1 = 0.f, a2 = 0.f, a3 = 0.f;
        int i = start + slot;
        for (; i + 12 < end; i += 16) {
            int s0 = g_srcs[i];
            int s1 = g_srcs[i + 4];
            int s2 = g_srcs[i + 8];
            int s3 = g_srcs[i + 12];
            a0 += g_h2[s0 * 8 + f];
            a1 += g_h2[s1 * 8 + f];
            a2 += g_h2[s2 * 8 + f];
            a3 += g_h2[s3 * 8 + f];
        }
        for (; i < end; i += 4) a0 += g_h2[g_srcs[i] * 8 + f];
        float acc = (a0 + a1) + (a2 + a3);
        acc += __shfl_xor_sync(0xffffffffu, acc, 16);
        acc += __shfl_xor_sync(0xffffffffu, acc, 8);

        float v = acc + b2f;
        float m = (f < 7) ? v : -3.0e38f;
#pragma unroll
        for (int d = 4; d; d >>= 1) m = fmaxf(m, __shfl_xor_sync(0xffffffffu, m, d));
        float ex = (f < 7) ? expf(v - m) : 0.f;
        float ssum = ex;
#pragma unroll
        for (int d = 4; d; d >>= 1) ssum += __shfl_xor_sync(0xffffffffu, ssum, d);
        float lse = m + logf(ssum);
        if (slot == 0 && f < 7) out[(size_t)n * 7 + f] = v - lse;
    }
}

// ----------------------------------------------------------------
// Inputs identified by element count (pairwise distinct):
//   x: 51,200,000  edge_index: 6,400,000  W1: 8,192  W2: 112  b1: 16  b2: 7
extern "C" void kernel_launch(void* const* d_in, const int* in_sizes, int n_in,
                              void* d_out, int out_size) {
    const float* x  = nullptr;
    const int*   ei = nullptr;
    const float* W1 = nullptr;
    const float* b1 = nullptr;
    const float* W2 = nullptr;
    const float* b2 = nullptr;

    for (int i = 0; i < n_in; i++) {
        switch (in_sizes[i]) {
            case N_NODES * N_FEAT: x  = (const float*)d_in[i]; break;
            case 2 * N_EDGES:      ei = (const int*)d_in[i];   break;
            case N_FEAT * N_HID:   W1 = (const float*)d_in[i]; break;
            case N_HID:            b1 = (const float*)d_in[i]; break;
            case N_HID * N_CLS:    W2 = (const float*)d_in[i]; break;
            case N_CLS:            b2 = (const float*)d_in[i]; break;
            default: break;
        }
    }
    float* out = (float*)d_out;

    hist_kernel<<<EDGEB, 256>>>(ei);
    scan_kernel<<<SCAN_GRID, SCAN_BLK>>>();
    fill_kernel<<<EDGEB, 256>>>(ei);
    gemm1_kernel<<<304, 256>>>(x, W1);
    gather1_kernel<<<1184, 256>>>(W2, b1);
    gather2_kernel<<<1184, 256>>>(b2, out);
}

// round 14
// speedup vs baseline: 1.1691x; 1.0677x over previous
#include <cuda_runtime.h>

#define N_NODES 100000
#define N_EDGES 3200000
#define N_FEAT  512
#define N_HID   16
#define N_CLS   7

#define SCAN_BLK   1024
#define SCAN_GRID  98            // 98*1024 = 100352 >= N_NODES
#define SCAN_TOT   (SCAN_GRID * SCAN_BLK)
#define EDGEB      3125          // 3125 * 256 threads * 4 edges = 3.2M
#define GROWS      8             // rows per gemm tile

// Scratch (device globals; no allocation allowed).
// Zero-recycling invariants (device globals zero-initialized at load):
//  - g_deg zeroed by scan_kernel after consumption -> next call's hist starts at 0.
//  - g_scan_pkt zeroed by hist_kernel block 0 (serialized before scan).
__device__ __align__(128) float g_h   [N_NODES * N_HID];  // x @ W1
__device__ __align__(128) float g_h2  [N_NODES * 8];      // relu(agg1+b1) @ W2, padded
__device__ __align__(128) int   g_deg [SCAN_TOT];         // per-dst degree
__device__ __align__(128) int   g_off [SCAN_TOT];         // CSR offsets (exclusive scan)
__device__ __align__(128) int   g_pos [N_EDGES];          // within-segment position
__device__ __align__(128) int   g_srcs[N_EDGES];          // CSR: src ids grouped by dst
__device__ __align__(128) volatile unsigned long long g_scan_pkt[SCAN_GRID]; // (flag<<32)|sum

typedef unsigned long long u64;

__device__ __forceinline__ u64 pack2(float a, float b) {
    u64 r; asm("mov.b64 %0, {%1,%2};" : "=l"(r) : "f"(a), "f"(b)); return r;
}
__device__ __forceinline__ void unpack2(u64 v, float& a, float& b) {
    asm("mov.b64 {%0,%1}, %2;" : "=f"(a), "=f"(b) : "l"(v));
}
__device__ __forceinline__ void ffma2(u64& d, u64 a, u64 b) {
    asm("fma.rn.f32x2 %0, %1, %2, %0;" : "+l"(d) : "l"(a), "l"(b));
}
__device__ __forceinline__ void fadd2(u64& d, u64 a) {
    asm("add.rn.f32x2 %0, %0, %1;" : "+l"(d) : "l"(a));
}

// ---------------------------------------------------------------- degree histogram (+position)
__global__ void __launch_bounds__(256, 8)
hist_kernel(const int* __restrict__ ei) {
    if (blockIdx.x == 0 && threadIdx.x < SCAN_GRID)
        g_scan_pkt[threadIdx.x] = 0ull;          // reset lookback state for this call
    int e0 = (blockIdx.x * 256 + threadIdx.x) * 4;
    if (e0 >= N_EDGES) return;
    int4 d4 = *reinterpret_cast<const int4*>(ei + N_EDGES + e0);
    int4 p4;
    p4.x = atomicAdd(&g_deg[d4.x], 1);
    p4.y = atomicAdd(&g_deg[d4.y], 1);
    p4.z = atomicAdd(&g_deg[d4.z], 1);
    p4.w = atomicAdd(&g_deg[d4.w], 1);
    *reinterpret_cast<int4*>(g_pos + e0) = p4;
}

// ---------------------------------------------------------------- single-pass scan (decoupled lookback)
// 98 blocks, all resident in wave 1 -> lookback cannot deadlock.
// Also re-zeroes g_deg for the next call.
__global__ void __launch_bounds__(SCAN_BLK, 1)
scan_kernel() {
    __shared__ int sd[SCAN_BLK];
    __shared__ int sh_prefix;
    const int t = threadIdx.x, b = blockIdx.x;
    const int g = b * SCAN_BLK + t;
    const int val = g_deg[g];
    g_deg[g] = 0;                                // recycle for next call
    sd[t] = val;
    __syncthreads();
    for (int d = 1; d < SCAN_BLK; d <<= 1) {
        int tmp = (t >= d) ? sd[t - d] : 0;
        __syncthreads();
        if (t >= d) sd[t] += tmp;
        __syncthreads();
    }
    const int incl  = sd[t];
    const int total = sd[SCAN_BLK - 1];

    if (t == 0) {
        if (b == 0) { sh_prefix = 0; g_scan_pkt[0] = (2ull << 32) | (unsigned)total; }
        else        { g_scan_pkt[b] = (1ull << 32) | (unsigned)total; }
    }
    __syncthreads();

    if (b > 0 && t < 32) {     // warp 0 lookback, 32-wide windows
        const int lane = t;
        int running = 0;
        int p = b - 1;
        for (;;) {
            int idx = p - lane;
            u64 pkt = 0ull;
            if (idx >= 0) {
                do { pkt = g_scan_pkt[idx]; } while ((unsigned)(pkt >> 32) == 0u);
            }
            unsigned flag = (unsigned)(pkt >> 32);
            unsigned mi = __ballot_sync(0xffffffffu, (idx >= 0) && (flag == 2u));
            int l2 = mi ? (__ffs(mi) - 1) : 32;
            int contrib = ((idx >= 0) && (lane <= l2)) ? (int)(unsigned)pkt : 0;
#pragma unroll
            for (int d = 16; d; d >>= 1) contrib += __shfl_xor_sync(0xffffffffu, contrib, d);
            running += contrib;
            if (mi) break;
            p -= 32;
        }
        if (lane == 0) {
            sh_prefix = running;
            g_scan_pkt[b] = (2ull << 32) | (unsigned)(running + total);
        }
    }
    __syncthreads();
    g_off[g] = sh_prefix + incl - val;
}

// ---------------------------------------------------------------- CSR fill (atomic-free)
__global__ void __launch_bounds__(256, 8)
fill_kernel(const int* __restrict__ ei) {
    int e0 = (blockIdx.x * 256 + threadIdx.x) * 4;
    if (e0 >= N_EDGES) return;
    int4 s4 = *reinterpret_cast<const int4*>(ei + e0);
    int4 d4 = *reinterpret_cast<const int4*>(ei + N_EDGES + e0);
    int4 p4 = *reinterpret_cast<const int4*>(g_pos + e0);
    g_srcs[g_off[d4.x] + p4.x] = s4.x;
    g_srcs[g_off[d4.y] + p4.y] = s4.y;
    g_srcs[g_off[d4.z] + p4.z] = s4.z;
    g_srcs[g_off[d4.w] + p4.w] = s4.w;
}

// ---------------------------------------------------------------- GEMM1: h = x @ W1
// 8-row tiles in smem, plain row-major float4 (NO swizzle). Warp w: row-group
// s = w>>2 (4 rows), col-quad q = w&3 (4 cols). Lane l owns
// k in { j4*128 + 4l .. +3 : j4=0..3 } so the FMA-phase smem read address is
// row*128 + j4*32 + l -> conflict-free by construction. W in 32 packed-f32x2
// regs. Software-pipelined prefetch. Reduction: reduce-scatter first step
// (1 SHFL), then 4 butterfly steps on one u64; lanes 0/16 store the pairs.
__global__ void __launch_bounds__(256, 2)
gemm1_kernel(const float* __restrict__ x, const float* __restrict__ W1) {
    __shared__ float4 xs[GROWS * 128];   // 16KB, row-major
    const int tid = threadIdx.x;
    const int w = tid >> 5, l = tid & 31;
    const int q = w & 3, s = w >> 2;
    const bool hi = (l & 16) != 0;

    u64 wr0[16], wr1[16];
#pragma unroll
    for (int j4 = 0; j4 < 4; j4++) {
#pragma unroll
        for (int e = 0; e < 4; e++) {
            int k = j4 * 128 + 4 * l + e;
            float4 wv = *reinterpret_cast<const float4*>(W1 + k * 16 + q * 4);
            wr0[j4 * 4 + e] = pack2(wv.x, wv.y);
            wr1[j4 * 4 + e] = pack2(wv.z, wv.w);
        }
    }

    const float4* x4 = reinterpret_cast<const float4*>(x);
    const int ntiles = N_NODES / GROWS;   // 12500

    int tile = blockIdx.x;
    float4 v0, v1, v2, v3;
    if (tile < ntiles) {
        size_t base = (size_t)tile * (GROWS * 128);
        v0 = x4[base + tid];
        v1 = x4[base + 256 + tid];
        v2 = x4[base + 512 + tid];
        v3 = x4[base + 768 + tid];
    }

    while (tile < ntiles) {
        __syncthreads();      // prior tile's readers done
        xs[tid]       = v0;
        xs[tid + 256] = v1;
        xs[tid + 512] = v2;
        xs[tid + 768] = v3;
        __syncthreads();

        const int next = tile + gridDim.x;
        if (next < ntiles) {  // prefetch next tile during compute
            size_t base = (size_t)next * (GROWS * 128);
            v0 = x4[base + tid];
            v1 = x4[base + 256 + tid];
            v2 = x4[base + 512 + tid];
            v3 = x4[base + 768 + tid];
        }

        u64 a0[4], a1[4];
#pragma unroll
        for (int r = 0; r < 4; r++) { a0[r] = 0ull; a1[r] = 0ull; }
#pragma unroll
        for (int r = 0; r < 4; r++) {
            const int row = s * 4 + r;
#pragma unroll
            for (int j4 = 0; j4 < 4; j4++) {
                float4 xv = xs[row * 128 + j4 * 32 + l];   // consecutive granules
                u64 xx;
                xx = pack2(xv.x, xv.x); ffma2(a0[r], xx, wr0[j4*4+0]); ffma2(a1[r], xx, wr1[j4*4+0]);
                xx = pack2(xv.y, xv.y); ffma2(a0[r], xx, wr0[j4*4+1]); ffma2(a1[r], xx, wr1[j4*4+1]);
                xx = pack2(xv.z, xv.z); ffma2(a0[r], xx, wr0[j4*4+2]); ffma2(a1[r], xx, wr1[j4*4+2]);
                xx = pack2(xv.w, xv.w); ffma2(a0[r], xx, wr0[j4*4+3]); ffma2(a1[r], xx, wr1[j4*4+3]);
            }
        }
        // Reduction per row: reduce-scatter step (d=16) splits pair0/pair1
        // across lane halves, then 4 butterfly steps on a single u64.
#pragma unroll
        for (int r = 0; r < 4; r++) {
            u64 sel  = hi ? a0[r] : a1[r];          // the half we give away
            u64 keep = hi ? a1[r] : a0[r];          // the half we own
            u64 t = __shfl_xor_sync(0xffffffffu, sel, 16);
            fadd2(keep, t);
#pragma unroll
            for (int d = 8; d; d >>= 1) {
                u64 tt = __shfl_xor_sync(0xffffffffu, keep, d);
                fadd2(keep, tt);
            }
            // lane 0 holds cols (4q,4q+1); lane 16 holds cols (4q+2,4q+3)
            if ((l & 15) == 0) {
                float c0, c1; unpack2(keep, c0, c1);
                float2* hp = reinterpret_cast<float2*>(
                    g_h + (tile * GROWS + s * 4 + r) * 16 + q * 4 + (hi ? 2 : 0));
                *hp = make_float2(c0, c1);
            }
        }
        tile = next;
    }
}

// ---------------------------------------------------------------- gather1 + fused relu/W2
// Warp per node. Lane = slot*16 + f: feature in lane (coalesced row reads), 2 edge slots.
__global__ void __launch_bounds__(256, 8)
gather1_kernel(const float* __restrict__ W2, const float* __restrict__ b1) {
    const int lane = threadIdx.x & 31;
    const int wid  = threadIdx.x >> 5;
    const int f    = lane & 15;
    const int slot = lane >> 4;
    const int warp_global = blockIdx.x * 8 + wid;
    const int n_warps = gridDim.x * 8;

    float w2r[7];
#pragma unroll
    for (int cc = 0; cc < 7; cc++) w2r[cc] = __ldg(W2 + f * 7 + cc);
    const float b1f = __ldg(b1 + f);

    for (int n = warp_global; n < N_NODES; n += n_warps) {
        const int start = g_off[n];
        const int end   = g_off[n + 1];

        float a0 = 0.f, a1 = 0.f, a2 = 0.f, a3 = 0.f;
        int i = start + slot;
        for (; i + 6 < end; i += 8) {
            int s0 = g_srcs[i];
            int s1 = g_srcs[i + 2];
            int s2 = g_srcs[i + 4];
            int s3 = g_srcs[i + 6];
            a0 += g_h[s0 * 16 + f];
            a1 += g_h[s1 * 16 + f];
            a2 += g_h[s2 * 16 + f];
            a3 += g_h[s3 * 16 + f];
        }
        for (; i < end; i += 2) a0 += g_h[g_srcs[i] * 16 + f];
        float acc = (a0 + a1) + (a2 + a3);
        acc += __shfl_xor_sync(0xffffffffu, acc, 16);

        float r = fmaxf(acc + b1f, 0.f);
        float po[7];
#pragma unroll
        for (int cc = 0; cc < 7; cc++) po[cc] = r * w2r[cc];
#pragma unroll
        for (int d = 8; d; d >>= 1) {
#pragma unroll
            for (int cc = 0; cc < 7; cc++)
                po[cc] += __shfl_xor_sync(0xffffffffu, po[cc], d);
        }
        if (lane == 0) {
            float4* op = reinterpret_cast<float4*>(g_h2) + n * 2;
            op[0] = make_float4(po[0], po[1], po[2], po[3]);
            op[1] = make_float4(po[4], po[5], po[6], 0.f);
        }
    }
}

// ---------------------------------------------------------------- gather2 + fused log_softmax
__global__ void __launch_bounds__(256, 8)
gather2_kernel(const float* __restrict__ b2, float* __restrict__ out) {
    const int lane = threadIdx.x & 31;
    const int wid  = threadIdx.x >> 5;
    const int f    = lane & 7;
    const int slot = lane >> 3;        // 0..3
    const int warp_global = blockIdx.x * 8 + wid;
    const int n_warps = gridDim.x * 8;

    const float b2f = (f < 7) ? __ldg(b2 + f) : 0.f;

    for (int n = warp_global; n < N_NODES; n += n_warps) {
        const int start = g_off[n];
        const int end   = g_off[n + 1];

        float a0 = 0.f, a1 = 0.f, a2 = 0.f, a3 = 0.f;
        int i = start + slot;
        for (; i + 12 < end; i += 16) {
            int s0 = g_srcs[i];
            int s1 = g_srcs[i + 4];
            int s2 = g_srcs[i + 8];
            int s3 = g_srcs[i + 12];
            a0 += g_h2[s0 * 8 + f];
            a1 += g_h2[s1 * 8 + f];
            a2 += g_h2[s2 * 8 + f];
            a3 += g_h2[s3 * 8 + f];
        }
        for (; i < end; i += 4) a0 += g_h2[g_srcs[i] * 8 + f];
        float acc = (a0 + a1) + (a2 + a3);
        acc += __shfl_xor_sync(0xffffffffu, acc, 16);
        acc += __shfl_xor_sync(0xffffffffu, acc, 8);

        float v = acc + b2f;
        float m = (f < 7) ? v : -3.0e38f;
#pragma unroll
        for (int d = 4; d; d >>= 1) m = fmaxf(m, __shfl_xor_sync(0xffffffffu, m, d));
        float ex = (f < 7) ? expf(v - m) : 0.f;
        float ssum = ex;
#pragma unroll
        for (int d = 4; d; d >>= 1) ssum += __shfl_xor_sync(0xffffffffu, ssum, d);
        float lse = m + logf(ssum);
        if (slot == 0 && f < 7) out[(size_t)n * 7 + f] = v - lse;
    }
}

// ----------------------------------------------------------------
// Inputs identified by element count (pairwise distinct):
//   x: 51,200,000  edge_index: 6,400,000  W1: 8,192  W2: 112  b1: 16  b2: 7
extern "C" void kernel_launch(void* const* d_in, const int* in_sizes, int n_in,
                              void* d_out, int out_size) {
    const float* x  = nullptr;
    const int*   ei = nullptr;
    const float* W1 = nullptr;
    const float* b1 = nullptr;
    const float* W2 = nullptr;
    const float* b2 = nullptr;

    for (int i = 0; i < n_in; i++) {
        switch (in_sizes[i]) {
            case N_NODES * N_FEAT: x  = (const float*)d_in[i]; break;
            case 2 * N_EDGES:      ei = (const int*)d_in[i];   break;
            case N_FEAT * N_HID:   W1 = (const float*)d_in[i]; break;
            case N_HID:            b1 = (const float*)d_in[i]; break;
            case N_HID * N_CLS:    W2 = (const float*)d_in[i]; break;
            case N_CLS:            b2 = (const float*)d_in[i]; break;
            default: break;
        }
    }
    float* out = (float*)d_out;

    hist_kernel<<<EDGEB, 256>>>(ei);
    scan_kernel<<<SCAN_GRID, SCAN_BLK>>>();
    fill_kernel<<<EDGEB, 256>>>(ei);
    gemm1_kernel<<<304, 256>>>(x, W1);
    gather1_kernel<<<1216, 256>>>(W2, b1);
    gather2_kernel<<<1216, 256>>>(b2, out);
}